// round 15
// baseline (speedup 1.0000x reference)
#include <cuda_runtime.h>
#include <math.h>
#include <stdint.h>

#define NM     64      // number of matrices (B*H)
#define MATN   128     // matrix dim (D)
#define SLEN   2048    // sequence length
#define RANK   64
#define ROUNDS 127     // MATN - 1
#define TOTR   (6 * ROUNDS + 64)   // "6.5 sweeps"
#define LDA    144     // A stride: 144 % 32 == 16 -> conflict-free (2 rows x 16 cols tiles)
#define LDW    132     // W stride: conflict-free float4 under (p + 2s) mapping
#define NPART  8       // gram split-K parts

// Scratch (device globals; no allocations allowed)
__device__ float g_G4[NPART][NM][MATN][MATN];  // partial Gram matrices (32 MB)
__device__ float g_P[NM][MATN][MATN];          // projectors (4 MB)

typedef unsigned long long u64t;
__device__ __forceinline__ u64t pack2(float lo, float hi) {
    u64t r; asm("mov.b64 %0,{%1,%2};" : "=l"(r) : "f"(lo), "f"(hi)); return r;
}
__device__ __forceinline__ u64t mul2(u64t a, u64t b) {
    u64t r; asm("mul.rn.f32x2 %0,%1,%2;" : "=l"(r) : "l"(a), "l"(b)); return r;
}
__device__ __forceinline__ u64t fma2(u64t a, u64t b, u64t c) {
    u64t r; asm("fma.rn.f32x2 %0,%1,%2,%3;" : "=l"(r) : "l"(a), "l"(b), "l"(c)); return r;
}

// ---- cluster / mbarrier helpers -------------------------------------------
__device__ __forceinline__ uint32_t ctarank() {
    uint32_t r; asm("mov.u32 %0, %%cluster_ctarank;" : "=r"(r)); return r;
}
__device__ __forceinline__ uint32_t mapa_rank(uint32_t laddr, uint32_t rank) {
    uint32_t r;
    asm("mapa.shared::cluster.u32 %0, %1, %2;" : "=r"(r) : "r"(laddr), "r"(rank));
    return r;
}
__device__ __forceinline__ void mbar_init(uint32_t a, uint32_t cnt) {
    asm volatile("mbarrier.init.shared.b64 [%0], %1;" :: "r"(a), "r"(cnt) : "memory");
}
__device__ __forceinline__ void mbar_arrive_remote(uint32_t remAddr) {
    asm volatile("mbarrier.arrive.shared::cluster.b64 _, [%0];" :: "r"(remAddr) : "memory");
}
__device__ __forceinline__ void mbar_arrive_expect_tx(uint32_t addr, uint32_t bytes) {
    asm volatile("mbarrier.arrive.expect_tx.shared::cta.b64 _, [%0], %1;"
                 :: "r"(addr), "r"(bytes) : "memory");
}
__device__ __forceinline__ void mbar_wait(uint32_t addr, uint32_t parity) {
    asm volatile(
        "{\n\t"
        ".reg .pred P;\n"
        "WAIT_%=:\n\t"
        "mbarrier.try_wait.parity.acquire.cluster.shared::cta.b64 P, [%0], %1, 0x989680;\n\t"
        "@P bra.uni DONE_%=;\n\t"
        "bra.uni WAIT_%=;\n"
        "DONE_%=:\n\t"
        "}"
        :: "r"(addr), "r"(parity) : "memory");
}
// st.async: write 8B into peer-CTA smem, tx-signaling the peer's mbarrier.
__device__ __forceinline__ void st_async_b64(uint32_t remAddr, u64t v, uint32_t remMbar) {
    asm volatile(
        "st.async.shared::cluster.mbarrier::complete_tx::bytes.b64 [%0], %1, [%2];"
        :: "r"(remAddr), "l"(v), "r"(remMbar) : "memory");
}
__device__ __forceinline__ void st_cluster_f(uint32_t addr, float v) {
    asm volatile("st.shared::cluster.f32 [%0], %1;" :: "r"(addr), "f"(v) : "memory");
}
#define CLUSTER_SYNC() do { \
    asm volatile("barrier.cluster.arrive.aligned;" ::: "memory"); \
    asm volatile("barrier.cluster.wait.aligned;" ::: "memory"); \
} while (0)

// Chess-tournament pairing: round rr in [0,127), pair index i in [0,64)
__device__ __forceinline__ void pair_pq(int i, int rr, int& p, int& q) {
    if (i == 0) { p = 0; }
    else { int x = i - 1 + rr; if (x >= 127) x -= 127; p = 1 + x; }
    int y = 126 - i + rr; if (y >= 127) y -= 127; q = 1 + y;
}

// Jacobi rotation (c,s) for pair (p,q) from A (stride LDA). Fast-math chain.
__device__ __forceinline__ void jac_rot_cs(const float* A, int p, int q,
                                           float& c, float& s) {
    float app = A[p * LDA + p], aqq = A[q * LDA + q], apq = A[p * LDA + q];
    c = 1.f; s = 0.f;
    float scl = fabsf(app) + fabsf(aqq);
    if (fabsf(apq) > 1e-12f * scl + 1e-38f) {
        float tau = __fdividef(aqq - app, 2.f * apq);
        float u = fmaf(tau, tau, 1.f);
        float root = u * rsqrtf(u);                 // = sqrt(u), MUFU
        float tt = __fdividef(1.f, fabsf(tau) + root);
        tt = (tau < 0.f) ? -tt : tt;
        c = rsqrtf(fmaf(tt, tt, 1.f));
        s = tt * c;
    }
}

// ---------------------------------------------------------------------------
// Kernel 1: partial Gram  G_part = X_partᵀ X_part   (grid: NM x NPART, 256 thr)
// ---------------------------------------------------------------------------
__global__ __launch_bounds__(256) void gram_kernel(const float* __restrict__ X) {
    __shared__ float Xs[64][MATN];
    const int m = blockIdx.x, part = blockIdx.y;
    const int t = threadIdx.x;
    const int a0 = (t >> 4) * 8, b0 = (t & 15) * 8;
    float acc[8][8];
#pragma unroll
    for (int i = 0; i < 8; i++)
#pragma unroll
        for (int j = 0; j < 8; j++) acc[i][j] = 0.f;

    const float* Xm = X + ((size_t)m * SLEN + (size_t)part * (SLEN / NPART)) * MATN;
    for (int ch = 0; ch < SLEN / NPART / 64; ch++) {
        const float4* src = (const float4*)(Xm + (size_t)ch * 64 * MATN);
        float4* dst = (float4*)&Xs[0][0];
#pragma unroll
        for (int j = 0; j < 8; j++) dst[t + 256 * j] = src[t + 256 * j];
        __syncthreads();
#pragma unroll 4
        for (int s = 0; s < 64; s++) {
            float4 a40 = *(const float4*)&Xs[s][a0];
            float4 a41 = *(const float4*)&Xs[s][a0 + 4];
            float4 b40 = *(const float4*)&Xs[s][b0];
            float4 b41 = *(const float4*)&Xs[s][b0 + 4];
            float av[8] = {a40.x, a40.y, a40.z, a40.w, a41.x, a41.y, a41.z, a41.w};
            float bv[8] = {b40.x, b40.y, b40.z, b40.w, b41.x, b41.y, b41.z, b41.w};
#pragma unroll
            for (int i = 0; i < 8; i++)
#pragma unroll
                for (int j = 0; j < 8; j++) acc[i][j] += av[i] * bv[j];
        }
        __syncthreads();
    }
    float* Gp = &g_G4[part][m][0][0];
#pragma unroll
    for (int i = 0; i < 8; i++) {
        float4 v0 = {acc[i][0], acc[i][1], acc[i][2], acc[i][3]};
        float4 v1 = {acc[i][4], acc[i][5], acc[i][6], acc[i][7]};
        *(float4*)&Gp[(a0 + i) * MATN + b0] = v0;
        *(float4*)&Gp[(a0 + i) * MATN + b0 + 4] = v1;
    }
}

// ---------------------------------------------------------------------------
// Kernel 2: Jacobi eigensolver, 2-CTA cluster per matrix, software-pipelined.
//   CTA rank 0: holds A; round r:  [FMA(r)+STS] bar [phase0(r+1) || prefetch
//               pair-indices+A-loads for r+1] bar.
//   CTA rank 1: holds W = Vᵀ; applies rotations; builds projector.
// Rotations ship as 8B (c,s) via st.async.b64; p,q recomputed locally.
// smem byte layout (identical in both CTAs):
//   [0,1024)    rotc[2][64] float2 (c,s)
//   [2048,2064) fullb[2]  (tx mbarriers; live in CTA1)
//   [2064,2080) emptyb[2] (mbarriers; live in CTA0)
//   [2080,2592) ev[128]
//   [2592,2848) sidx[64]
//   [3072, ...) big[]: A (128x144) in CTA0 / W (128x132) in CTA1
// ---------------------------------------------------------------------------
#define BAR_FULL  2048
#define BAR_EMPTY 2064
#define EV_OFF    2080
#define SIDX_OFF  2592
#define BIG_OFF   3072
#define JAC_SMEM  (BIG_OFF + MATN * LDA * 4)
#define ROT_TX    512   // 64 pairs x 8B per slot

__global__ __launch_bounds__(1024) __cluster_dims__(2, 1, 1)
void jacobi_kernel() {
    extern __shared__ float smf[];
    char* smb = (char*)smf;
    float2* rotc = (float2*)smb;               // [2][64] (c,s)
    float*  ev   = (float*)(smb + EV_OFF);
    int*    sidx = (int*)(smb + SIDX_OFF);
    float*  big  = (float*)(smb + BIG_OFF);

    const int m = blockIdx.y, t = threadIdx.x;
    const uint32_t rank = ctarank();
    const uint32_t sbase = (uint32_t)__cvta_generic_to_shared(smb);

    if (t == 0) {
        mbar_init(sbase + BAR_FULL, 1);
        mbar_init(sbase + BAR_FULL + 8, 1);
        mbar_init(sbase + BAR_EMPTY, 1);
        mbar_init(sbase + BAR_EMPTY + 8, 1);
        if (rank == 1) {
            mbar_arrive_expect_tx(sbase + BAR_FULL, ROT_TX);
            mbar_arrive_expect_tx(sbase + BAR_FULL + 8, ROT_TX);
        }
    }
    __syncthreads();
    CLUSTER_SYNC();   // barriers visible cluster-wide before any remote op

    const int pa  = t >> 4;   // pair index (0..63)
    const int sub = t & 15;   // sub-slot (0..15)

    if (rank == 0) {
        // ===== A-CTA =====
        const uint32_t rem_rotc  = mapa_rank(sbase, 1);
        const uint32_t rem_full0 = mapa_rank(sbase + BAR_FULL, 1);
        const uint32_t rem_full1 = mapa_rank(sbase + BAR_FULL + 8, 1);

        for (int idx = t; idx < MATN * MATN; idx += 1024) {
            int i = idx >> 7, j = idx & 127;
            float a = 0.f;
#pragma unroll
            for (int pp = 0; pp < NPART; pp++) a += g_G4[pp][m][i][j];
            big[i * LDA + j] = a;
        }
        __syncthreads();

        // Prologue phase0(0): rotations -> local slot0 + remote slot0
        if (t < 64) {
            int p, q; pair_pq(t, 0, p, q);
            float c, s; jac_rot_cs(big, p, q, c, s);
            rotc[t] = make_float2(c, s);
            st_async_b64(rem_rotc + t * 8, pack2(c, s), rem_full0);
        }
        __syncthreads();

        // Prefetch for round 0: pair indices + A values into registers
        int rowP, rowQ, col[8];
        float v[16];
        {
            int p, q; pair_pq(pa, 0, p, q);
            rowP = p * LDA; rowQ = q * LDA;
#pragma unroll
            for (int k = 0; k < 4; k++) {
                int pb, qb; pair_pq(sub + (k << 4), 0, pb, qb);
                col[2 * k] = pb; col[2 * k + 1] = qb;
            }
#pragma unroll
            for (int k = 0; k < 4; k++) {
                v[4 * k + 0] = big[rowP + col[2 * k]];
                v[4 * k + 1] = big[rowP + col[2 * k + 1]];
                v[4 * k + 2] = big[rowQ + col[2 * k]];
                v[4 * k + 3] = big[rowQ + col[2 * k + 1]];
            }
        }

        int phE0 = 0, phE1 = 1;   // producer empty-parity per slot
        int rr = 0;

        for (int r = 0; r < TOTR; r++) {
            // Early empty-wait for NEXT round's slot (released a round ago).
            if (t < 64 && r + 1 < TOTR) {
                int s_n = (r + 1) & 1;
                int par = s_n ? phE1 : phE0;
                mbar_wait(sbase + BAR_EMPTY + s_n * 8, par);
                if (s_n) phE1 ^= 1; else phE0 ^= 1;
            }

            const float2* rcs = rotc + ((r & 1) << 6);
            float2 ra = rcs[pa];
            const float ca = ra.x, sa = ra.y;

            // Phase 1a compute on prefetched registers + batched stores
#pragma unroll
            for (int k = 0; k < 4; k++) {
                float2 rb = rcs[sub + (k << 4)];
                float a0 = v[4 * k], b0 = v[4 * k + 1], c0 = v[4 * k + 2], d0 = v[4 * k + 3];
                float r00 = ca * a0 - sa * c0, r01 = ca * b0 - sa * d0;
                float r10 = sa * a0 + ca * c0, r11 = sa * b0 + ca * d0;
                float n00 = rb.x * r00 - rb.y * r01, n01 = rb.y * r00 + rb.x * r01;
                float n10 = rb.x * r10 - rb.y * r11, n11 = rb.y * r10 + rb.x * r11;
                big[rowP + col[2 * k]] = n00; big[rowP + col[2 * k + 1]] = n01;
                big[rowQ + col[2 * k]] = n10; big[rowQ + col[2 * k + 1]] = n11;
            }
            __syncthreads();   // A(r) final

            if (r + 1 < TOTR) {
                int rr1 = rr + 1; if (rr1 == ROUNDS) rr1 = 0;
                int s = (r + 1) & 1;

                // phase0(r+1) on warps 0-1 (overlapped with prefetch below)
                if (t < 64) {
                    int p, q; pair_pq(t, rr1, p, q);
                    float c, sn; jac_rot_cs(big, p, q, c, sn);
                    rotc[(s << 6) + t] = make_float2(c, sn);
                    st_async_b64(rem_rotc + ((s << 6) + t) * 8, pack2(c, sn),
                                 s ? rem_full1 : rem_full0);
                }

                // Prefetch pair indices + A loads for round r+1 (all warps)
                {
                    int p, q; pair_pq(pa, rr1, p, q);
                    rowP = p * LDA; rowQ = q * LDA;
#pragma unroll
                    for (int k = 0; k < 4; k++) {
                        int pb, qb; pair_pq(sub + (k << 4), rr1, pb, qb);
                        col[2 * k] = pb; col[2 * k + 1] = qb;
                    }
#pragma unroll
                    for (int k = 0; k < 4; k++) {
                        v[4 * k + 0] = big[rowP + col[2 * k]];
                        v[4 * k + 1] = big[rowP + col[2 * k + 1]];
                        v[4 * k + 2] = big[rowQ + col[2 * k]];
                        v[4 * k + 3] = big[rowQ + col[2 * k + 1]];
                    }
                }
                __syncthreads();   // rot(r+1) visible; prefetch loads in flight
                rr = rr1;
            }
        }

        if (t < MATN) {
            float e = big[t * LDA + t];
            st_cluster_f(mapa_rank(sbase + EV_OFF + t * 4, 1), e);
        }
        CLUSTER_SYNC();   // publishes ev to CTA1
    } else {
        // ===== W-CTA =====
        for (int idx = t; idx < MATN * MATN; idx += 1024) {
            int i = idx >> 7, j = idx & 127;
            big[i * LDW + j] = (i == j) ? 1.f : 0.f;
        }
        __syncthreads();

        int phF0 = 0, phF1 = 0;   // consumer full-parity per slot
        int rr = 0;

        for (int r = 0; r < TOTR; r++) {
            int s = r & 1;
            {
                int par = s ? phF1 : phF0;
                mbar_wait(sbase + BAR_FULL + s * 8, par);   // ALL threads
                if (s) phF1 ^= 1; else phF0 ^= 1;
            }
            if (t == 0)   // re-arm this slot for its next use
                mbar_arrive_expect_tx(sbase + BAR_FULL + s * 8, ROT_TX);

            float2 ra = rotc[(s << 6) + pa];
            __syncthreads();   // all rot reads done before releasing the slot
            if (t == 0) mbar_arrive_remote(mapa_rank(sbase + BAR_EMPTY + s * 8, 0));

            const float ca = ra.x, sa = ra.y;
            int p_a, q_a; pair_pq(pa, rr, p_a, q_a);
            rr++; if (rr == ROUNDS) rr = 0;

            // Phase 1b: W = Vᵀ row rotation, packed f32x2 (8 cols per thread)
            ulonglong2* Wp = (ulonglong2*)(big + p_a * LDW + (sub << 3));
            ulonglong2* Wq = (ulonglong2*)(big + q_a * LDW + (sub << 3));
            const u64t ca2  = pack2(ca, ca);
            const u64t sa2  = pack2(sa, sa);
            const u64t nsa2 = pack2(-sa, -sa);
#pragma unroll
            for (int i = 0; i < 2; i++) {
                ulonglong2 x = Wp[i], y = Wq[i];
                ulonglong2 nx, ny;
                nx.x = fma2(ca2, x.x, mul2(nsa2, y.x));
                nx.y = fma2(ca2, x.y, mul2(nsa2, y.y));
                ny.x = fma2(sa2, x.x, mul2(ca2, y.x));
                ny.y = fma2(sa2, x.y, mul2(ca2, y.y));
                Wp[i] = nx; Wq[i] = ny;
            }
        }

        CLUSTER_SYNC();   // ev now visible locally

        if (t < MATN) {
            float e = ev[t]; int rk = 0;
            for (int j = 0; j < MATN; j++) {
                float o = ev[j];
                if (o > e || (o == e && j < t)) rk++;
            }
            if (rk < RANK) sidx[rk] = t;
        }
        __syncthreads();

        // P = Σ over 64 selected rows of W: W[r,:]ᵀ W[r,:]
        const int i0 = (t >> 5) * 4, j0 = (t & 31) * 4;
        float acc[4][4];
#pragma unroll
        for (int i = 0; i < 4; i++)
#pragma unroll
            for (int j = 0; j < 4; j++) acc[i][j] = 0.f;

        for (int ii = 0; ii < RANK; ii++) {
            int row = sidx[ii];
            const float* Wr = big + row * LDW;
            float4 va4 = *(const float4*)&Wr[i0];
            float4 vb4 = *(const float4*)&Wr[j0];
            float va[4] = {va4.x, va4.y, va4.z, va4.w};
            float vb[4] = {vb4.x, vb4.y, vb4.z, vb4.w};
#pragma unroll
            for (int i = 0; i < 4; i++)
#pragma unroll
                for (int j = 0; j < 4; j++) acc[i][j] += va[i] * vb[j];
        }
        float* Pp = &g_P[m][0][0];
#pragma unroll
        for (int i = 0; i < 4; i++) {
            float4 vv = {acc[i][0], acc[i][1], acc[i][2], acc[i][3]};
            *(float4*)&Pp[(i0 + i) * MATN + j0] = vv;
        }
    }
}

// ---------------------------------------------------------------------------
// Kernel 3: Y = X · P  (grid: NM x 32 row-blocks of 64 rows, 256 threads)
// ---------------------------------------------------------------------------
#define LDX 129
#define REC_SMEM ((64 * LDX + MATN * MATN) * 4)

__global__ __launch_bounds__(256) void recon_kernel(const float* __restrict__ X,
                                                    float* __restrict__ out) {
    extern __shared__ float sm[];
    float* Xs = sm;              // 64 x 129
    float* Ps = sm + 64 * LDX;   // 128 x 128
    const int m = blockIdx.x, rb = blockIdx.y;
    const int t = threadIdx.x;

    const float* Xm = X + ((size_t)m * SLEN + (size_t)rb * 64) * MATN;
    for (int idx = t; idx < 64 * MATN; idx += 256) {
        int rI = idx >> 7, c = idx & 127;
        Xs[rI * LDX + c] = Xm[idx];
    }
    const float4* Pg = (const float4*)&g_P[m][0][0];
    float4* Pd = (float4*)Ps;
    for (int idx = t; idx < MATN * MATN / 4; idx += 256) Pd[idx] = Pg[idx];
    __syncthreads();

    const int r0 = (t >> 4) * 4, c0 = (t & 15) * 8;
    float acc[4][8];
#pragma unroll
    for (int i = 0; i < 4; i++)
#pragma unroll
        for (int j = 0; j < 8; j++) acc[i][j] = 0.f;

    for (int k = 0; k < MATN; k++) {
        float xv[4];
#pragma unroll
        for (int i = 0; i < 4; i++) xv[i] = Xs[(r0 + i) * LDX + k];
        float4 p0 = *(const float4*)&Ps[k * MATN + c0];
        float4 p1 = *(const float4*)&Ps[k * MATN + c0 + 4];
        float pv[8] = {p0.x, p0.y, p0.z, p0.w, p1.x, p1.y, p1.z, p1.w};
#pragma unroll
        for (int i = 0; i < 4; i++)
#pragma unroll
            for (int j = 0; j < 8; j++) acc[i][j] += xv[i] * pv[j];
    }

    float* Om = out + ((size_t)m * SLEN + (size_t)rb * 64) * MATN;
#pragma unroll
    for (int i = 0; i < 4; i++) {
        float4 v0 = {acc[i][0], acc[i][1], acc[i][2], acc[i][3]};
        float4 v1 = {acc[i][4], acc[i][5], acc[i][6], acc[i][7]};
        *(float4*)&Om[(r0 + i) * MATN + c0] = v0;
        *(float4*)&Om[(r0 + i) * MATN + c0 + 4] = v1;
    }
}

// ---------------------------------------------------------------------------
extern "C" void kernel_launch(void* const* d_in, const int* in_sizes, int n_in,
                              void* d_out, int out_size) {
    const float* X = (const float*)d_in[0];   // kv_cache fp32 (4,16,2048,128)
    float* out = (float*)d_out;               // fp32, same shape

    cudaFuncSetAttribute(jacobi_kernel, cudaFuncAttributeMaxDynamicSharedMemorySize, JAC_SMEM);
    cudaFuncSetAttribute(recon_kernel,  cudaFuncAttributeMaxDynamicSharedMemorySize, REC_SMEM);

    gram_kernel<<<dim3(NM, NPART), 256>>>(X);
    jacobi_kernel<<<dim3(2, NM), 1024, JAC_SMEM>>>();
    recon_kernel<<<dim3(NM, 32), 256, REC_SMEM>>>(X, out);
}

// round 16
// speedup vs baseline: 1.4692x; 1.4692x over previous
#include <cuda_runtime.h>
#include <math.h>
#include <stdint.h>

#define NM     64      // number of matrices (B*H)
#define MATN   128     // matrix dim (D)
#define SLEN   2048    // sequence length
#define RANK   64
#define ROUNDS 127     // MATN - 1
#define TOTR   (6 * ROUNDS + 64)   // "6.5 sweeps"
#define LDA    144     // A stride: 144 % 32 == 16 -> conflict-free (2 rows x 16 cols tiles)
#define LDW    132     // W stride: conflict-free float4 under (p + 2s) mapping
#define NPART  8       // gram split-K parts

// Scratch (device globals; no allocations allowed)
__device__ float g_G4[NPART][NM][MATN][MATN];  // partial Gram matrices (32 MB)
__device__ float g_P[NM][MATN][MATN];          // projectors (4 MB)

typedef unsigned long long u64t;
__device__ __forceinline__ u64t pack2(float lo, float hi) {
    u64t r; asm("mov.b64 %0,{%1,%2};" : "=l"(r) : "f"(lo), "f"(hi)); return r;
}
__device__ __forceinline__ u64t mul2(u64t a, u64t b) {
    u64t r; asm("mul.rn.f32x2 %0,%1,%2;" : "=l"(r) : "l"(a), "l"(b)); return r;
}
__device__ __forceinline__ u64t fma2(u64t a, u64t b, u64t c) {
    u64t r; asm("fma.rn.f32x2 %0,%1,%2,%3;" : "=l"(r) : "l"(a), "l"(b), "l"(c)); return r;
}

// ---- cluster / mbarrier helpers -------------------------------------------
__device__ __forceinline__ uint32_t ctarank() {
    uint32_t r; asm("mov.u32 %0, %%cluster_ctarank;" : "=r"(r)); return r;
}
__device__ __forceinline__ uint32_t mapa_rank(uint32_t laddr, uint32_t rank) {
    uint32_t r;
    asm("mapa.shared::cluster.u32 %0, %1, %2;" : "=r"(r) : "r"(laddr), "r"(rank));
    return r;
}
__device__ __forceinline__ void mbar_init(uint32_t a, uint32_t cnt) {
    asm volatile("mbarrier.init.shared.b64 [%0], %1;" :: "r"(a), "r"(cnt) : "memory");
}
__device__ __forceinline__ void mbar_arrive_remote(uint32_t remAddr) {
    asm volatile("mbarrier.arrive.shared::cluster.b64 _, [%0];" :: "r"(remAddr) : "memory");
}
__device__ __forceinline__ void mbar_arrive_expect_tx(uint32_t addr, uint32_t bytes) {
    asm volatile("mbarrier.arrive.expect_tx.shared::cta.b64 _, [%0], %1;"
                 :: "r"(addr), "r"(bytes) : "memory");
}
__device__ __forceinline__ void mbar_wait(uint32_t addr, uint32_t parity) {
    asm volatile(
        "{\n\t"
        ".reg .pred P;\n"
        "WAIT_%=:\n\t"
        "mbarrier.try_wait.parity.acquire.cluster.shared::cta.b64 P, [%0], %1, 0x989680;\n\t"
        "@P bra.uni DONE_%=;\n\t"
        "bra.uni WAIT_%=;\n"
        "DONE_%=:\n\t"
        "}"
        :: "r"(addr), "r"(parity) : "memory");
}
// st.async: write 8B into peer-CTA smem, tx-signaling the peer's mbarrier.
__device__ __forceinline__ void st_async_b64(uint32_t remAddr, u64t v, uint32_t remMbar) {
    asm volatile(
        "st.async.shared::cluster.mbarrier::complete_tx::bytes.b64 [%0], %1, [%2];"
        :: "r"(remAddr), "l"(v), "r"(remMbar) : "memory");
}
__device__ __forceinline__ void st_cluster_f(uint32_t addr, float v) {
    asm volatile("st.shared::cluster.f32 [%0], %1;" :: "r"(addr), "f"(v) : "memory");
}
#define CLUSTER_SYNC() do { \
    asm volatile("barrier.cluster.arrive.aligned;" ::: "memory"); \
    asm volatile("barrier.cluster.wait.aligned;" ::: "memory"); \
} while (0)

// Chess-tournament pairing: round rr in [0,127), pair index i in [0,64)
__device__ __forceinline__ void pair_pq(int i, int rr, int& p, int& q) {
    if (i == 0) { p = 0; }
    else { int x = i - 1 + rr; if (x >= 127) x -= 127; p = 1 + x; }
    int y = 126 - i + rr; if (y >= 127) y -= 127; q = 1 + y;
}

// Jacobi rotation (c,s) for pair (p,q) from A (stride LDA). Fast-math chain.
__device__ __forceinline__ void jac_rot_cs(const float* A, int p, int q,
                                           float& c, float& s) {
    float app = A[p * LDA + p], aqq = A[q * LDA + q], apq = A[p * LDA + q];
    c = 1.f; s = 0.f;
    float scl = fabsf(app) + fabsf(aqq);
    if (fabsf(apq) > 1e-12f * scl + 1e-38f) {
        float tau = __fdividef(aqq - app, 2.f * apq);
        float u = fmaf(tau, tau, 1.f);
        float root = u * rsqrtf(u);                 // = sqrt(u), MUFU
        float tt = __fdividef(1.f, fabsf(tau) + root);
        tt = (tau < 0.f) ? -tt : tt;
        c = rsqrtf(fmaf(tt, tt, 1.f));
        s = tt * c;
    }
}

// ---------------------------------------------------------------------------
// Kernel 1: partial Gram  G_part = X_partᵀ X_part   (grid: NM x NPART, 256 thr)
// ---------------------------------------------------------------------------
__global__ __launch_bounds__(256) void gram_kernel(const float* __restrict__ X) {
    __shared__ float Xs[64][MATN];
    const int m = blockIdx.x, part = blockIdx.y;
    const int t = threadIdx.x;
    const int a0 = (t >> 4) * 8, b0 = (t & 15) * 8;
    float acc[8][8];
#pragma unroll
    for (int i = 0; i < 8; i++)
#pragma unroll
        for (int j = 0; j < 8; j++) acc[i][j] = 0.f;

    const float* Xm = X + ((size_t)m * SLEN + (size_t)part * (SLEN / NPART)) * MATN;
    for (int ch = 0; ch < SLEN / NPART / 64; ch++) {
        const float4* src = (const float4*)(Xm + (size_t)ch * 64 * MATN);
        float4* dst = (float4*)&Xs[0][0];
#pragma unroll
        for (int j = 0; j < 8; j++) dst[t + 256 * j] = src[t + 256 * j];
        __syncthreads();
#pragma unroll 4
        for (int s = 0; s < 64; s++) {
            float4 a40 = *(const float4*)&Xs[s][a0];
            float4 a41 = *(const float4*)&Xs[s][a0 + 4];
            float4 b40 = *(const float4*)&Xs[s][b0];
            float4 b41 = *(const float4*)&Xs[s][b0 + 4];
            float av[8] = {a40.x, a40.y, a40.z, a40.w, a41.x, a41.y, a41.z, a41.w};
            float bv[8] = {b40.x, b40.y, b40.z, b40.w, b41.x, b41.y, b41.z, b41.w};
#pragma unroll
            for (int i = 0; i < 8; i++)
#pragma unroll
                for (int j = 0; j < 8; j++) acc[i][j] += av[i] * bv[j];
        }
        __syncthreads();
    }
    float* Gp = &g_G4[part][m][0][0];
#pragma unroll
    for (int i = 0; i < 8; i++) {
        float4 v0 = {acc[i][0], acc[i][1], acc[i][2], acc[i][3]};
        float4 v1 = {acc[i][4], acc[i][5], acc[i][6], acc[i][7]};
        *(float4*)&Gp[(a0 + i) * MATN + b0] = v0;
        *(float4*)&Gp[(a0 + i) * MATN + b0 + 4] = v1;
    }
}

// ---------------------------------------------------------------------------
// Kernel 2: Jacobi eigensolver, 2-CTA cluster per matrix, pipelined with a
// precomputed pair-index LUT (plut[127][64], uint16 p|q<<8 — data-independent).
//   CTA rank 0: holds A; round r: [FMA(r) on prefetched regs + STS] bar
//               [phase0(r+1) on warps 0-1 || all warps prefetch A(r+1) via plut] bar
//   CTA rank 1: holds W = Vᵀ; applies rotations; builds projector.
// Rotations ship as 8B (c,s) via st.async.b64; p,q from each CTA's plut.
// smem byte layout (identical in both CTAs):
//   [0,1024)      rotc[2][64] float2 (c,s)
//   [2048,2064)   fullb[2]  (tx mbarriers; live in CTA1)
//   [2064,2080)   emptyb[2] (mbarriers; live in CTA0)
//   [2080,2592)   ev[128]
//   [2592,2848)   sidx[64]
//   [3072,19328)  plut[127*64] uint16
//   [19456, ...)  big[]: A (128x144) in CTA0 / W (128x132) in CTA1
// ---------------------------------------------------------------------------
#define BAR_FULL  2048
#define BAR_EMPTY 2064
#define EV_OFF    2080
#define SIDX_OFF  2592
#define PLUT_OFF  3072
#define BIG_OFF   19456
#define JAC_SMEM  (BIG_OFF + MATN * LDA * 4)
#define ROT_TX    512   // 64 pairs x 8B per slot

__global__ __launch_bounds__(1024) __cluster_dims__(2, 1, 1)
void jacobi_kernel() {
    extern __shared__ float smf[];
    char* smb = (char*)smf;
    float2*   rotc = (float2*)smb;             // [2][64] (c,s)
    float*    ev   = (float*)(smb + EV_OFF);
    int*      sidx = (int*)(smb + SIDX_OFF);
    uint16_t* plut = (uint16_t*)(smb + PLUT_OFF);
    float*    big  = (float*)(smb + BIG_OFF);

    const int m = blockIdx.y, t = threadIdx.x;
    const uint32_t rank = ctarank();
    const uint32_t sbase = (uint32_t)__cvta_generic_to_shared(smb);

    if (t == 0) {
        mbar_init(sbase + BAR_FULL, 1);
        mbar_init(sbase + BAR_FULL + 8, 1);
        mbar_init(sbase + BAR_EMPTY, 1);
        mbar_init(sbase + BAR_EMPTY + 8, 1);
        if (rank == 1) {
            mbar_arrive_expect_tx(sbase + BAR_FULL, ROT_TX);
            mbar_arrive_expect_tx(sbase + BAR_FULL + 8, ROT_TX);
        }
    }
    // Build pair-index LUT (both CTAs; data-independent)
    for (int idx = t; idx < ROUNDS * 64; idx += 1024) {
        int rr = idx >> 6, i = idx & 63;
        int p, q; pair_pq(i, rr, p, q);
        plut[idx] = (uint16_t)(p | (q << 8));
    }
    __syncthreads();
    CLUSTER_SYNC();   // barriers visible cluster-wide before any remote op

    const int pa  = t >> 4;   // pair index (0..63)
    const int sub = t & 15;   // sub-slot (0..15)

    if (rank == 0) {
        // ===== A-CTA =====
        const uint32_t rem_rotc  = mapa_rank(sbase, 1);
        const uint32_t rem_full0 = mapa_rank(sbase + BAR_FULL, 1);
        const uint32_t rem_full1 = mapa_rank(sbase + BAR_FULL + 8, 1);

        for (int idx = t; idx < MATN * MATN; idx += 1024) {
            int i = idx >> 7, j = idx & 127;
            float a = 0.f;
#pragma unroll
            for (int pp = 0; pp < NPART; pp++) a += g_G4[pp][m][i][j];
            big[i * LDA + j] = a;
        }
        __syncthreads();

        // Prologue phase0(0): rotations -> local slot0 + remote slot0
        if (t < 64) {
            uint16_t pr = plut[t];
            int p = pr & 255, q = pr >> 8;
            float c, s; jac_rot_cs(big, p, q, c, s);
            rotc[t] = make_float2(c, s);
            st_async_b64(rem_rotc + t * 8, pack2(c, s), rem_full0);
        }
        __syncthreads();

        // Prefetch for round 0: indices from plut row 0 + A values -> regs
        int rowP, rowQ, col[8];
        float v[16];
        {
            uint16_t pr = plut[pa];
            rowP = (pr & 255) * LDA; rowQ = (pr >> 8) * LDA;
#pragma unroll
            for (int k = 0; k < 4; k++) {
                uint16_t pc = plut[sub + (k << 4)];
                col[2 * k] = pc & 255; col[2 * k + 1] = pc >> 8;
            }
#pragma unroll
            for (int k = 0; k < 4; k++) {
                v[4 * k + 0] = big[rowP + col[2 * k]];
                v[4 * k + 1] = big[rowP + col[2 * k + 1]];
                v[4 * k + 2] = big[rowQ + col[2 * k]];
                v[4 * k + 3] = big[rowQ + col[2 * k + 1]];
            }
        }

        int phE0 = 0, phE1 = 1;   // producer empty-parity per slot
        int rr = 0;

        for (int r = 0; r < TOTR; r++) {
            // Early empty-wait for NEXT round's slot (released a round ago).
            if (t < 64 && r + 1 < TOTR) {
                int s_n = (r + 1) & 1;
                int par = s_n ? phE1 : phE0;
                mbar_wait(sbase + BAR_EMPTY + s_n * 8, par);
                if (s_n) phE1 ^= 1; else phE0 ^= 1;
            }

            const float2* rcs = rotc + ((r & 1) << 6);
            float2 ra = rcs[pa];
            const float ca = ra.x, sa = ra.y;

            // Phase 1a compute on prefetched registers + batched stores
#pragma unroll
            for (int k = 0; k < 4; k++) {
                float2 rb = rcs[sub + (k << 4)];
                float a0 = v[4 * k], b0 = v[4 * k + 1], c0 = v[4 * k + 2], d0 = v[4 * k + 3];
                float r00 = ca * a0 - sa * c0, r01 = ca * b0 - sa * d0;
                float r10 = sa * a0 + ca * c0, r11 = sa * b0 + ca * d0;
                float n00 = rb.x * r00 - rb.y * r01, n01 = rb.y * r00 + rb.x * r01;
                float n10 = rb.x * r10 - rb.y * r11, n11 = rb.y * r10 + rb.x * r11;
                big[rowP + col[2 * k]] = n00; big[rowP + col[2 * k + 1]] = n01;
                big[rowQ + col[2 * k]] = n10; big[rowQ + col[2 * k + 1]] = n11;
            }
            __syncthreads();   // A(r) final

            if (r + 1 < TOTR) {
                int rr1 = rr + 1; if (rr1 == ROUNDS) rr1 = 0;
                int s = (r + 1) & 1;
                const uint16_t* prow = plut + (rr1 << 6);

                // phase0(r+1) on warps 0-1 (overlapped with prefetch below)
                if (t < 64) {
                    uint16_t pr = prow[t];
                    int p = pr & 255, q = pr >> 8;
                    float c, sn; jac_rot_cs(big, p, q, c, sn);
                    rotc[(s << 6) + t] = make_float2(c, sn);
                    st_async_b64(rem_rotc + ((s << 6) + t) * 8, pack2(c, sn),
                                 s ? rem_full1 : rem_full0);
                }

                // Prefetch indices + A values for round r+1 (all warps, via plut)
                {
                    uint16_t pr = prow[pa];
                    rowP = (pr & 255) * LDA; rowQ = (pr >> 8) * LDA;
#pragma unroll
                    for (int k = 0; k < 4; k++) {
                        uint16_t pc = prow[sub + (k << 4)];
                        col[2 * k] = pc & 255; col[2 * k + 1] = pc >> 8;
                    }
#pragma unroll
                    for (int k = 0; k < 4; k++) {
                        v[4 * k + 0] = big[rowP + col[2 * k]];
                        v[4 * k + 1] = big[rowP + col[2 * k + 1]];
                        v[4 * k + 2] = big[rowQ + col[2 * k]];
                        v[4 * k + 3] = big[rowQ + col[2 * k + 1]];
                    }
                }
                __syncthreads();   // rot(r+1) visible; prefetched values in regs
                rr = rr1;
            }
        }

        if (t < MATN) {
            float e = big[t * LDA + t];
            st_cluster_f(mapa_rank(sbase + EV_OFF + t * 4, 1), e);
        }
        CLUSTER_SYNC();   // publishes ev to CTA1
    } else {
        // ===== W-CTA =====
        for (int idx = t; idx < MATN * MATN; idx += 1024) {
            int i = idx >> 7, j = idx & 127;
            big[i * LDW + j] = (i == j) ? 1.f : 0.f;
        }
        __syncthreads();

        int phF0 = 0, phF1 = 0;   // consumer full-parity per slot
        int rr = 0;

        for (int r = 0; r < TOTR; r++) {
            int s = r & 1;
            {
                int par = s ? phF1 : phF0;
                mbar_wait(sbase + BAR_FULL + s * 8, par);   // ALL threads
                if (s) phF1 ^= 1; else phF0 ^= 1;
            }
            if (t == 0)   // re-arm this slot for its next use
                mbar_arrive_expect_tx(sbase + BAR_FULL + s * 8, ROT_TX);

            float2 ra = rotc[(s << 6) + pa];
            __syncthreads();   // all rot reads done before releasing the slot
            if (t == 0) mbar_arrive_remote(mapa_rank(sbase + BAR_EMPTY + s * 8, 0));

            const float ca = ra.x, sa = ra.y;
            uint16_t pr = plut[(rr << 6) + pa];
            int p_a = pr & 255, q_a = pr >> 8;
            rr++; if (rr == ROUNDS) rr = 0;

            // Phase 1b: W = Vᵀ row rotation, packed f32x2 (8 cols per thread)
            ulonglong2* Wp = (ulonglong2*)(big + p_a * LDW + (sub << 3));
            ulonglong2* Wq = (ulonglong2*)(big + q_a * LDW + (sub << 3));
            const u64t ca2  = pack2(ca, ca);
            const u64t sa2  = pack2(sa, sa);
            const u64t nsa2 = pack2(-sa, -sa);
#pragma unroll
            for (int i = 0; i < 2; i++) {
                ulonglong2 x = Wp[i], y = Wq[i];
                ulonglong2 nx, ny;
                nx.x = fma2(ca2, x.x, mul2(nsa2, y.x));
                nx.y = fma2(ca2, x.y, mul2(nsa2, y.y));
                ny.x = fma2(sa2, x.x, mul2(ca2, y.x));
                ny.y = fma2(sa2, x.y, mul2(ca2, y.y));
                Wp[i] = nx; Wq[i] = ny;
            }
        }

        CLUSTER_SYNC();   // ev now visible locally

        if (t < MATN) {
            float e = ev[t]; int rk = 0;
            for (int j = 0; j < MATN; j++) {
                float o = ev[j];
                if (o > e || (o == e && j < t)) rk++;
            }
            if (rk < RANK) sidx[rk] = t;
        }
        __syncthreads();

        // P = Σ over 64 selected rows of W: W[r,:]ᵀ W[r,:]
        const int i0 = (t >> 5) * 4, j0 = (t & 31) * 4;
        float acc[4][4];
#pragma unroll
        for (int i = 0; i < 4; i++)
#pragma unroll
            for (int j = 0; j < 4; j++) acc[i][j] = 0.f;

        for (int ii = 0; ii < RANK; ii++) {
            int row = sidx[ii];
            const float* Wr = big + row * LDW;
            float4 va4 = *(const float4*)&Wr[i0];
            float4 vb4 = *(const float4*)&Wr[j0];
            float va[4] = {va4.x, va4.y, va4.z, va4.w};
            float vb[4] = {vb4.x, vb4.y, vb4.z, vb4.w};
#pragma unroll
            for (int i = 0; i < 4; i++)
#pragma unroll
                for (int j = 0; j < 4; j++) acc[i][j] += va[i] * vb[j];
        }
        float* Pp = &g_P[m][0][0];
#pragma unroll
        for (int i = 0; i < 4; i++) {
            float4 vv = {acc[i][0], acc[i][1], acc[i][2], acc[i][3]};
            *(float4*)&Pp[(i0 + i) * MATN + j0] = vv;
        }
    }
}

// ---------------------------------------------------------------------------
// Kernel 3: Y = X · P  (grid: NM x 32 row-blocks of 64 rows, 256 threads)
// ---------------------------------------------------------------------------
#define LDX 129
#define REC_SMEM ((64 * LDX + MATN * MATN) * 4)

__global__ __launch_bounds__(256) void recon_kernel(const float* __restrict__ X,
                                                    float* __restrict__ out) {
    extern __shared__ float sm[];
    float* Xs = sm;              // 64 x 129
    float* Ps = sm + 64 * LDX;   // 128 x 128
    const int m = blockIdx.x, rb = blockIdx.y;
    const int t = threadIdx.x;

    const float* Xm = X + ((size_t)m * SLEN + (size_t)rb * 64) * MATN;
    for (int idx = t; idx < 64 * MATN; idx += 256) {
        int rI = idx >> 7, c = idx & 127;
        Xs[rI * LDX + c] = Xm[idx];
    }
    const float4* Pg = (const float4*)&g_P[m][0][0];
    float4* Pd = (float4*)Ps;
    for (int idx = t; idx < MATN * MATN / 4; idx += 256) Pd[idx] = Pg[idx];
    __syncthreads();

    const int r0 = (t >> 4) * 4, c0 = (t & 15) * 8;
    float acc[4][8];
#pragma unroll
    for (int i = 0; i < 4; i++)
#pragma unroll
        for (int j = 0; j < 8; j++) acc[i][j] = 0.f;

    for (int k = 0; k < MATN; k++) {
        float xv[4];
#pragma unroll
        for (int i = 0; i < 4; i++) xv[i] = Xs[(r0 + i) * LDX + k];
        float4 p0 = *(const float4*)&Ps[k * MATN + c0];
        float4 p1 = *(const float4*)&Ps[k * MATN + c0 + 4];
        float pv[8] = {p0.x, p0.y, p0.z, p0.w, p1.x, p1.y, p1.z, p1.w};
#pragma unroll
        for (int i = 0; i < 4; i++)
#pragma unroll
            for (int j = 0; j < 8; j++) acc[i][j] += xv[i] * pv[j];
    }

    float* Om = out + ((size_t)m * SLEN + (size_t)rb * 64) * MATN;
#pragma unroll
    for (int i = 0; i < 4; i++) {
        float4 v0 = {acc[i][0], acc[i][1], acc[i][2], acc[i][3]};
        float4 v1 = {acc[i][4], acc[i][5], acc[i][6], acc[i][7]};
        *(float4*)&Om[(r0 + i) * MATN + c0] = v0;
        *(float4*)&Om[(r0 + i) * MATN + c0 + 4] = v1;
    }
}

// ---------------------------------------------------------------------------
extern "C" void kernel_launch(void* const* d_in, const int* in_sizes, int n_in,
                              void* d_out, int out_size) {
    const float* X = (const float*)d_in[0];   // kv_cache fp32 (4,16,2048,128)
    float* out = (float*)d_out;               // fp32, same shape

    cudaFuncSetAttribute(jacobi_kernel, cudaFuncAttributeMaxDynamicSharedMemorySize, JAC_SMEM);
    cudaFuncSetAttribute(recon_kernel,  cudaFuncAttributeMaxDynamicSharedMemorySize, REC_SMEM);

    gram_kernel<<<dim3(NM, NPART), 256>>>(X);
    jacobi_kernel<<<dim3(2, NM), 1024, JAC_SMEM>>>();
    recon_kernel<<<dim3(NM, 32), 256, REC_SMEM>>>(X, out);
}

// round 17
// speedup vs baseline: 1.5713x; 1.0694x over previous
#include <cuda_runtime.h>
#include <math.h>
#include <stdint.h>

#define NM     64      // number of matrices (B*H)
#define MATN   128     // matrix dim (D)
#define SLEN   2048    // sequence length
#define RANK   64
#define ROUNDS 127     // MATN - 1
#define TOTR   (6 * ROUNDS + 48)   // "6.375 sweeps"
#define LDA    144     // A stride: 144 % 32 == 16 -> conflict-free (2 rows x 16 cols tiles)
#define LDW    132     // W stride: conflict-free float4 under (p + 2s) mapping
#define NPART  8       // gram split-K parts

// Scratch (device globals; no allocations allowed)
__device__ float g_G4[NPART][NM][MATN][MATN];  // partial Gram matrices (32 MB)
__device__ float g_P[NM][MATN][MATN];          // projectors (4 MB)

typedef unsigned long long u64t;
__device__ __forceinline__ u64t pack2(float lo, float hi) {
    u64t r; asm("mov.b64 %0,{%1,%2};" : "=l"(r) : "f"(lo), "f"(hi)); return r;
}
__device__ __forceinline__ u64t mul2(u64t a, u64t b) {
    u64t r; asm("mul.rn.f32x2 %0,%1,%2;" : "=l"(r) : "l"(a), "l"(b)); return r;
}
__device__ __forceinline__ u64t fma2(u64t a, u64t b, u64t c) {
    u64t r; asm("fma.rn.f32x2 %0,%1,%2,%3;" : "=l"(r) : "l"(a), "l"(b), "l"(c)); return r;
}

// ---- cluster / mbarrier helpers -------------------------------------------
__device__ __forceinline__ uint32_t ctarank() {
    uint32_t r; asm("mov.u32 %0, %%cluster_ctarank;" : "=r"(r)); return r;
}
__device__ __forceinline__ uint32_t mapa_rank(uint32_t laddr, uint32_t rank) {
    uint32_t r;
    asm("mapa.shared::cluster.u32 %0, %1, %2;" : "=r"(r) : "r"(laddr), "r"(rank));
    return r;
}
__device__ __forceinline__ void mbar_init(uint32_t a, uint32_t cnt) {
    asm volatile("mbarrier.init.shared.b64 [%0], %1;" :: "r"(a), "r"(cnt) : "memory");
}
__device__ __forceinline__ void mbar_arrive_remote(uint32_t remAddr) {
    asm volatile("mbarrier.arrive.shared::cluster.b64 _, [%0];" :: "r"(remAddr) : "memory");
}
__device__ __forceinline__ void mbar_arrive_expect_tx(uint32_t addr, uint32_t bytes) {
    asm volatile("mbarrier.arrive.expect_tx.shared::cta.b64 _, [%0], %1;"
                 :: "r"(addr), "r"(bytes) : "memory");
}
__device__ __forceinline__ void mbar_wait(uint32_t addr, uint32_t parity) {
    asm volatile(
        "{\n\t"
        ".reg .pred P;\n"
        "WAIT_%=:\n\t"
        "mbarrier.try_wait.parity.acquire.cluster.shared::cta.b64 P, [%0], %1, 0x989680;\n\t"
        "@P bra.uni DONE_%=;\n\t"
        "bra.uni WAIT_%=;\n"
        "DONE_%=:\n\t"
        "}"
        :: "r"(addr), "r"(parity) : "memory");
}
// st.async: write 16B into peer-CTA smem, tx-signaling the peer's mbarrier.
__device__ __forceinline__ void st_async_f4(uint32_t remAddr, float4 v, uint32_t remMbar) {
    asm volatile(
        "st.async.shared::cluster.mbarrier::complete_tx::bytes.v4.f32 [%0], {%1,%2,%3,%4}, [%5];"
        :: "r"(remAddr), "f"(v.x), "f"(v.y), "f"(v.z), "f"(v.w), "r"(remMbar) : "memory");
}
__device__ __forceinline__ void st_cluster_f(uint32_t addr, float v) {
    asm volatile("st.shared::cluster.f32 [%0], %1;" :: "r"(addr), "f"(v) : "memory");
}
#define CLUSTER_SYNC() do { \
    asm volatile("barrier.cluster.arrive.aligned;" ::: "memory"); \
    asm volatile("barrier.cluster.wait.aligned;" ::: "memory"); \
} while (0)

// Chess-tournament pairing: round rr in [0,127), pair index i in [0,64)
__device__ __forceinline__ void pair_pq(int i, int rr, int& p, int& q) {
    if (i == 0) { p = 0; }
    else { int x = i - 1 + rr; if (x >= 127) x -= 127; p = 1 + x; }
    int y = 126 - i + rr; if (y >= 127) y -= 127; q = 1 + y;
}

// Jacobi rotation (c,s) for pair (p,q) from A (stride LDA). Fast-math chain.
__device__ __forceinline__ void jac_rot(const float* A, int rr, int i,
                                        float& c, float& s, int& p, int& q) {
    pair_pq(i, rr, p, q);
    float app = A[p * LDA + p], aqq = A[q * LDA + q], apq = A[p * LDA + q];
    c = 1.f; s = 0.f;
    float scl = fabsf(app) + fabsf(aqq);
    if (fabsf(apq) > 1e-12f * scl + 1e-38f) {
        float tau = __fdividef(aqq - app, 2.f * apq);
        float u = fmaf(tau, tau, 1.f);
        float root = u * rsqrtf(u);                 // = sqrt(u), MUFU
        float tt = __fdividef(1.f, fabsf(tau) + root);
        tt = (tau < 0.f) ? -tt : tt;
        c = rsqrtf(fmaf(tt, tt, 1.f));
        s = tt * c;
    }
}

// ---------------------------------------------------------------------------
// Kernel 1: partial Gram  G_part = X_partᵀ X_part   (grid: NM x NPART, 256 thr)
// ---------------------------------------------------------------------------
__global__ __launch_bounds__(256) void gram_kernel(const float* __restrict__ X) {
    __shared__ float Xs[64][MATN];
    const int m = blockIdx.x, part = blockIdx.y;
    const int t = threadIdx.x;
    const int a0 = (t >> 4) * 8, b0 = (t & 15) * 8;
    float acc[8][8];
#pragma unroll
    for (int i = 0; i < 8; i++)
#pragma unroll
        for (int j = 0; j < 8; j++) acc[i][j] = 0.f;

    const float* Xm = X + ((size_t)m * SLEN + (size_t)part * (SLEN / NPART)) * MATN;
    for (int ch = 0; ch < SLEN / NPART / 64; ch++) {
        const float4* src = (const float4*)(Xm + (size_t)ch * 64 * MATN);
        float4* dst = (float4*)&Xs[0][0];
#pragma unroll
        for (int j = 0; j < 8; j++) dst[t + 256 * j] = src[t + 256 * j];
        __syncthreads();
#pragma unroll 4
        for (int s = 0; s < 64; s++) {
            float4 a40 = *(const float4*)&Xs[s][a0];
            float4 a41 = *(const float4*)&Xs[s][a0 + 4];
            float4 b40 = *(const float4*)&Xs[s][b0];
            float4 b41 = *(const float4*)&Xs[s][b0 + 4];
            float av[8] = {a40.x, a40.y, a40.z, a40.w, a41.x, a41.y, a41.z, a41.w};
            float bv[8] = {b40.x, b40.y, b40.z, b40.w, b41.x, b41.y, b41.z, b41.w};
#pragma unroll
            for (int i = 0; i < 8; i++)
#pragma unroll
                for (int j = 0; j < 8; j++) acc[i][j] += av[i] * bv[j];
        }
        __syncthreads();
    }
    float* Gp = &g_G4[part][m][0][0];
#pragma unroll
    for (int i = 0; i < 8; i++) {
        float4 v0 = {acc[i][0], acc[i][1], acc[i][2], acc[i][3]};
        float4 v1 = {acc[i][4], acc[i][5], acc[i][6], acc[i][7]};
        *(float4*)&Gp[(a0 + i) * MATN + b0] = v0;
        *(float4*)&Gp[(a0 + i) * MATN + b0 + 4] = v1;
    }
}

// ---------------------------------------------------------------------------
// Kernel 2: Jacobi eigensolver, 2-CTA cluster per matrix (R14 structure).
//   CTA rank 0: holds A; rotations (phase 0) + full A update (phase 1a).
//   CTA rank 1: holds W = Vᵀ; applies rotations (phase 1b); builds projector.
// Phase 1a: ONE batch of 4 column-pairs — all loads issued before FMA/STS.
// ---------------------------------------------------------------------------
#define BAR_FULL  2048
#define BAR_EMPTY 2064
#define EV_OFF    2080
#define SIDX_OFF  2592
#define BIG_OFF   3072
#define JAC_SMEM  (BIG_OFF + MATN * LDA * 4)

__global__ __launch_bounds__(1024) __cluster_dims__(2, 1, 1)
void jacobi_kernel() {
    extern __shared__ float smf[];
    char* smb = (char*)smf;
    float4* rot  = (float4*)smb;
    float*  ev   = (float*)(smb + EV_OFF);
    int*    sidx = (int*)(smb + SIDX_OFF);
    float*  big  = (float*)(smb + BIG_OFF);

    const int m = blockIdx.y, t = threadIdx.x;
    const uint32_t rank = ctarank();
    const uint32_t sbase = (uint32_t)__cvta_generic_to_shared(smb);

    if (t == 0) {
        mbar_init(sbase + BAR_FULL, 1);
        mbar_init(sbase + BAR_FULL + 8, 1);
        mbar_init(sbase + BAR_EMPTY, 1);
        mbar_init(sbase + BAR_EMPTY + 8, 1);
        if (rank == 1) {
            mbar_arrive_expect_tx(sbase + BAR_FULL, 1024);
            mbar_arrive_expect_tx(sbase + BAR_FULL + 8, 1024);
        }
    }
    __syncthreads();
    CLUSTER_SYNC();   // barriers visible cluster-wide before any remote op

    const int pa  = t >> 4;   // pair index (0..63)
    const int sub = t & 15;   // sub-slot (0..15)

    if (rank == 0) {
        // ===== A-CTA =====
        const uint32_t rem_rot   = mapa_rank(sbase, 1);
        const uint32_t rem_full0 = mapa_rank(sbase + BAR_FULL, 1);
        const uint32_t rem_full1 = mapa_rank(sbase + BAR_FULL + 8, 1);

        for (int idx = t; idx < MATN * MATN; idx += 1024) {
            int i = idx >> 7, j = idx & 127;
            float a = 0.f;
#pragma unroll
            for (int pp = 0; pp < NPART; pp++) a += g_G4[pp][m][i][j];
            big[i * LDA + j] = a;
        }
        __syncthreads();

        if (t < 64) {
            float c, s; int p, q;
            jac_rot(big, 0, t, c, s, p, q);
            float4 v = make_float4(c, s, __int_as_float(p), __int_as_float(q));
            rot[t] = v;
            st_async_f4(rem_rot + t * 16, v, rem_full0);
        }
        __syncthreads();

        int phE0 = 0, phE1 = 1;   // producer empty-parity per slot
        int rr = 0;

        for (int r = 0; r < TOTR; r++) {
            // Early empty-wait for NEXT round's slot (released a round ago).
            if (t < 64 && r + 1 < TOTR) {
                int s_n = (r + 1) & 1;
                int par = s_n ? phE1 : phE0;
                mbar_wait(sbase + BAR_EMPTY + s_n * 8, par);
                if (s_n) phE1 ^= 1; else phE0 ^= 1;
            }

            float4* rots = rot + ((r & 1) << 6);
            float4 ra = rots[pa];
            const float ca = ra.x, sa = ra.y;
            const int p_a = __float_as_int(ra.z), q_a = __float_as_int(ra.w);
            float* Arp = big + p_a * LDA;
            float* Arq = big + q_a * LDA;

            // Phase 1a: single fully-batched update of 4 column-pairs.
            {
                float4 rb0 = rots[sub];
                float4 rb1 = rots[sub + 16];
                float4 rb2 = rots[sub + 32];
                float4 rb3 = rots[sub + 48];
                int p0 = __float_as_int(rb0.z), q0 = __float_as_int(rb0.w);
                int p1 = __float_as_int(rb1.z), q1 = __float_as_int(rb1.w);
                int p2 = __float_as_int(rb2.z), q2 = __float_as_int(rb2.w);
                int p3 = __float_as_int(rb3.z), q3 = __float_as_int(rb3.w);
                // 16 batched loads (no intervening stores)
                float a0 = Arp[p0], b0 = Arp[q0], c0 = Arq[p0], d0 = Arq[q0];
                float a1 = Arp[p1], b1 = Arp[q1], c1 = Arq[p1], d1 = Arq[q1];
                float a2 = Arp[p2], b2 = Arp[q2], c2 = Arq[p2], d2 = Arq[q2];
                float a3 = Arp[p3], b3 = Arp[q3], c3 = Arq[p3], d3 = Arq[q3];
                // rotate all 4 blocks
                float r00, r01, r10, r11;
                r00 = ca * a0 - sa * c0; r01 = ca * b0 - sa * d0;
                r10 = sa * a0 + ca * c0; r11 = sa * b0 + ca * d0;
                a0 = rb0.x * r00 - rb0.y * r01; b0 = rb0.y * r00 + rb0.x * r01;
                c0 = rb0.x * r10 - rb0.y * r11; d0 = rb0.y * r10 + rb0.x * r11;
                r00 = ca * a1 - sa * c1; r01 = ca * b1 - sa * d1;
                r10 = sa * a1 + ca * c1; r11 = sa * b1 + ca * d1;
                a1 = rb1.x * r00 - rb1.y * r01; b1 = rb1.y * r00 + rb1.x * r01;
                c1 = rb1.x * r10 - rb1.y * r11; d1 = rb1.y * r10 + rb1.x * r11;
                r00 = ca * a2 - sa * c2; r01 = ca * b2 - sa * d2;
                r10 = sa * a2 + ca * c2; r11 = sa * b2 + ca * d2;
                a2 = rb2.x * r00 - rb2.y * r01; b2 = rb2.y * r00 + rb2.x * r01;
                c2 = rb2.x * r10 - rb2.y * r11; d2 = rb2.y * r10 + rb2.x * r11;
                r00 = ca * a3 - sa * c3; r01 = ca * b3 - sa * d3;
                r10 = sa * a3 + ca * c3; r11 = sa * b3 + ca * d3;
                a3 = rb3.x * r00 - rb3.y * r01; b3 = rb3.y * r00 + rb3.x * r01;
                c3 = rb3.x * r10 - rb3.y * r11; d3 = rb3.y * r10 + rb3.x * r11;
                // 16 batched stores
                Arp[p0] = a0; Arp[q0] = b0; Arq[p0] = c0; Arq[q0] = d0;
                Arp[p1] = a1; Arp[q1] = b1; Arq[p1] = c1; Arq[q1] = d1;
                Arp[p2] = a2; Arp[q2] = b2; Arq[p2] = c2; Arq[q2] = d2;
                Arp[p3] = a3; Arp[q3] = b3; Arq[p3] = c3; Arq[q3] = d3;
            }
            __syncthreads();

            if (r + 1 < TOTR) {
                int s = (r + 1) & 1;
                if (t < 64) {
                    float c, sn; int p, q;
                    int rr1 = rr + 1; if (rr1 == ROUNDS) rr1 = 0;
                    jac_rot(big, rr1, t, c, sn, p, q);
                    float4 v = make_float4(c, sn, __int_as_float(p), __int_as_float(q));
                    rot[(s << 6) + t] = v;
                    st_async_f4(rem_rot + ((s << 6) + t) * 16, v,
                                s ? rem_full1 : rem_full0);
                }
                __syncthreads();   // local rot slot visible to next round's 1a
                rr++; if (rr == ROUNDS) rr = 0;
            }
        }

        if (t < MATN) {
            float e = big[t * LDA + t];
            st_cluster_f(mapa_rank(sbase + EV_OFF + t * 4, 1), e);
        }
        CLUSTER_SYNC();   // publishes ev to CTA1
    } else {
        // ===== W-CTA =====
        for (int idx = t; idx < MATN * MATN; idx += 1024) {
            int i = idx >> 7, j = idx & 127;
            big[i * LDW + j] = (i == j) ? 1.f : 0.f;
        }
        __syncthreads();

        int phF0 = 0, phF1 = 0;   // consumer full-parity per slot

        for (int r = 0; r < TOTR; r++) {
            int s = r & 1;
            {
                int par = s ? phF1 : phF0;
                mbar_wait(sbase + BAR_FULL + s * 8, par);   // ALL threads
                if (s) phF1 ^= 1; else phF0 ^= 1;
            }
            if (t == 0)   // re-arm this slot for its next use
                mbar_arrive_expect_tx(sbase + BAR_FULL + s * 8, 1024);

            float4 ra = rot[(s << 6) + pa];
            __syncthreads();   // all rot reads done before releasing the slot
            if (t == 0) mbar_arrive_remote(mapa_rank(sbase + BAR_EMPTY + s * 8, 0));

            const float ca = ra.x, sa = ra.y;
            const int p_a = __float_as_int(ra.z), q_a = __float_as_int(ra.w);

            // Phase 1b: W = Vᵀ row rotation, packed f32x2 (8 cols per thread)
            ulonglong2* Wp = (ulonglong2*)(big + p_a * LDW + (sub << 3));
            ulonglong2* Wq = (ulonglong2*)(big + q_a * LDW + (sub << 3));
            const u64t ca2  = pack2(ca, ca);
            const u64t sa2  = pack2(sa, sa);
            const u64t nsa2 = pack2(-sa, -sa);
#pragma unroll
            for (int i = 0; i < 2; i++) {
                ulonglong2 x = Wp[i], y = Wq[i];
                ulonglong2 nx, ny;
                nx.x = fma2(ca2, x.x, mul2(nsa2, y.x));
                nx.y = fma2(ca2, x.y, mul2(nsa2, y.y));
                ny.x = fma2(sa2, x.x, mul2(ca2, y.x));
                ny.y = fma2(sa2, x.y, mul2(ca2, y.y));
                Wp[i] = nx; Wq[i] = ny;
            }
        }

        CLUSTER_SYNC();   // ev now visible locally

        if (t < MATN) {
            float e = ev[t]; int rk = 0;
            for (int j = 0; j < MATN; j++) {
                float o = ev[j];
                if (o > e || (o == e && j < t)) rk++;
            }
            if (rk < RANK) sidx[rk] = t;
        }
        __syncthreads();

        // P = Σ over 64 selected rows of W: W[r,:]ᵀ W[r,:]
        const int i0 = (t >> 5) * 4, j0 = (t & 31) * 4;
        float acc[4][4];
#pragma unroll
        for (int i = 0; i < 4; i++)
#pragma unroll
            for (int j = 0; j < 4; j++) acc[i][j] = 0.f;

        for (int ii = 0; ii < RANK; ii++) {
            int row = sidx[ii];
            const float* Wr = big + row * LDW;
            float4 va4 = *(const float4*)&Wr[i0];
            float4 vb4 = *(const float4*)&Wr[j0];
            float va[4] = {va4.x, va4.y, va4.z, va4.w};
            float vb[4] = {vb4.x, vb4.y, vb4.z, vb4.w};
#pragma unroll
            for (int i = 0; i < 4; i++)
#pragma unroll
                for (int j = 0; j < 4; j++) acc[i][j] += va[i] * vb[j];
        }
        float* Pp = &g_P[m][0][0];
#pragma unroll
        for (int i = 0; i < 4; i++) {
            float4 vv = {acc[i][0], acc[i][1], acc[i][2], acc[i][3]};
            *(float4*)&Pp[(i0 + i) * MATN + j0] = vv;
        }
    }
}

// ---------------------------------------------------------------------------
// Kernel 3: Y = X · P  (grid: NM x 32 row-blocks of 64 rows, 256 threads)
// ---------------------------------------------------------------------------
#define LDX 129
#define REC_SMEM ((64 * LDX + MATN * MATN) * 4)

__global__ __launch_bounds__(256) void recon_kernel(const float* __restrict__ X,
                                                    float* __restrict__ out) {
    extern __shared__ float sm[];
    float* Xs = sm;              // 64 x 129
    float* Ps = sm + 64 * LDX;   // 128 x 128
    const int m = blockIdx.x, rb = blockIdx.y;
    const int t = threadIdx.x;

    const float* Xm = X + ((size_t)m * SLEN + (size_t)rb * 64) * MATN;
    for (int idx = t; idx < 64 * MATN; idx += 256) {
        int rI = idx >> 7, c = idx & 127;
        Xs[rI * LDX + c] = Xm[idx];
    }
    const float4* Pg = (const float4*)&g_P[m][0][0];
    float4* Pd = (float4*)Ps;
    for (int idx = t; idx < MATN * MATN / 4; idx += 256) Pd[idx] = Pg[idx];
    __syncthreads();

    const int r0 = (t >> 4) * 4, c0 = (t & 15) * 8;
    float acc[4][8];
#pragma unroll
    for (int i = 0; i < 4; i++)
#pragma unroll
        for (int j = 0; j < 8; j++) acc[i][j] = 0.f;

    for (int k = 0; k < MATN; k++) {
        float xv[4];
#pragma unroll
        for (int i = 0; i < 4; i++) xv[i] = Xs[(r0 + i) * LDX + k];
        float4 p0 = *(const float4*)&Ps[k * MATN + c0];
        float4 p1 = *(const float4*)&Ps[k * MATN + c0 + 4];
        float pv[8] = {p0.x, p0.y, p0.z, p0.w, p1.x, p1.y, p1.z, p1.w};
#pragma unroll
        for (int i = 0; i < 4; i++)
#pragma unroll
            for (int j = 0; j < 8; j++) acc[i][j] += xv[i] * pv[j];
    }

    float* Om = out + ((size_t)m * SLEN + (size_t)rb * 64) * MATN;
#pragma unroll
    for (int i = 0; i < 4; i++) {
        float4 v0 = {acc[i][0], acc[i][1], acc[i][2], acc[i][3]};
        float4 v1 = {acc[i][4], acc[i][5], acc[i][6], acc[i][7]};
        *(float4*)&Om[(r0 + i) * MATN + c0] = v0;
        *(float4*)&Om[(r0 + i) * MATN + c0 + 4] = v1;
    }
}

// ---------------------------------------------------------------------------
extern "C" void kernel_launch(void* const* d_in, const int* in_sizes, int n_in,
                              void* d_out, int out_size) {
    const float* X = (const float*)d_in[0];   // kv_cache fp32 (4,16,2048,128)
    float* out = (float*)d_out;               // fp32, same shape

    cudaFuncSetAttribute(jacobi_kernel, cudaFuncAttributeMaxDynamicSharedMemorySize, JAC_SMEM);
    cudaFuncSetAttribute(recon_kernel,  cudaFuncAttributeMaxDynamicSharedMemorySize, REC_SMEM);

    gram_kernel<<<dim3(NM, NPART), 256>>>(X);
    jacobi_kernel<<<dim3(2, NM), 1024, JAC_SMEM>>>();
    recon_kernel<<<dim3(NM, 32), 256, REC_SMEM>>>(X, out);
}